// round 13
// baseline (speedup 1.0000x reference)
#include <cuda_runtime.h>
#include <cstdint>

#define NB 2048
#define NF 64
#define NR 32
#define NP 16
#define NC 128

// ---------------- scratch ----------------
__device__ float g_wch [NB*1024];
__device__ float g_vch [NB*1024];
__device__ float g_vep0[NB*1024];
__device__ float g_vep2[NB*1024];
__device__ float g_Wk  [3*NB*1024];
__device__ float g_small[NB*264];

__device__ __forceinline__ float sigmoidf_(float x) { return 1.f/(1.f + __expf(-x)); }

// ---- 3xTF32 helpers (family-portable PTX, sm_80+) ----
__device__ __forceinline__ void tf32split_(float x, uint32_t& hi, uint32_t& lo) {
    uint32_t h;
    asm("cvt.rna.tf32.f32 %0, %1;" : "=r"(h) : "f"(x));
    float r = x - __uint_as_float(h);
    uint32_t l;
    asm("cvt.rna.tf32.f32 %0, %1;" : "=r"(l) : "f"(r));
    hi = h; lo = l;
}
__device__ __forceinline__ void mma_tf32_(float* c, const uint32_t* a, uint32_t b0, uint32_t b1) {
    asm volatile(
        "mma.sync.aligned.m16n8k8.row.col.f32.tf32.tf32.f32 "
        "{%0,%1,%2,%3}, {%4,%5,%6,%7}, {%8,%9}, {%0,%1,%2,%3};"
        : "+f"(c[0]), "+f"(c[1]), "+f"(c[2]), "+f"(c[3])
        : "r"(a[0]), "r"(a[1]), "r"(a[2]), "r"(a[3]), "r"(b0), "r"(b1));
}

// ---- small-projection column map (258 cols) ----
__device__ __forceinline__ const float* sp_col(int n, int& stride,
    const float* mod_W, const float* wdl_W, const float* wep_W,
    const float* wnc_W, const float* mb_W, const float* wnd_W, const float* wne_W)
{
    if (n < 96)  { stride = 96; return mod_W + n; }
    if (n < 112) { stride = 16; return wdl_W + (n-96); }
    if (n < 128) { stride = 64; return wep_W + (n-112)*4; }
    if (n < 144) { stride = 64; return wep_W + (n-128)*4 + 2; }
    if (n < 208) { stride = 64; return wnc_W + (n-144); }
    if (n < 256) { int idx = n-208; stride = 16; return mb_W + (idx>>4)*2048 + (idx&15); }
    if (n == 256){ stride = 1; return wnd_W; }
    stride = 1; return wne_W;
}
__device__ __forceinline__ float sp_bias(int n,
    const float* mod_b, const float* wdl_b, const float* wep_b,
    const float* wnc_b, const float* mb_b, const float* wnd_b, const float* wne_b)
{
    if (n < 96)  return mod_b[n];
    if (n < 112) return wdl_b[n-96];
    if (n < 128) return wep_b[(n-112)*4];
    if (n < 144) return wep_b[(n-128)*4 + 2];
    if (n < 208) return wnc_b[n-144];
    if (n < 256) return mb_b[n-208];
    if (n == 256) return wnd_b[0];
    return wne_b[0];
}

// smem layout (floats): A stride 36, B stride 136.
#define PA 36
#define PB 136
#define OFF_AHI 0
#define OFF_ALO (128*PA)
#define OFF_BHI (2*128*PA)
#define OFF_BLO (2*128*PA + 32*PB)
#define OFF_BIAS (2*128*PA + 2*32*PB)
#define SM_FLOATS (OFF_BIAS + 128)
#define SM_BYTES  (SM_FLOATS*4)

// =====================================================================
// Kernel 1: 7 big GEMMs + z=7 small-proj gather GEMM. 3xTF32 mma.sync.
// Unified per-thread column pointers + register-prefetch pipelining.
// =====================================================================
__global__ __launch_bounds__(256, 2) void proj_tc(
    const float* __restrict__ ctx,
    const float* __restrict__ wch_W, const float* __restrict__ wch_b,
    const float* __restrict__ vch_W, const float* __restrict__ vch_b,
    const float* __restrict__ vep_W, const float* __restrict__ vep_b,
    const float* __restrict__ m_W,   const float* __restrict__ m_Wb,
    const float* __restrict__ mod_W, const float* __restrict__ mod_b,
    const float* __restrict__ wdl_W, const float* __restrict__ wdl_b,
    const float* __restrict__ wep_W, const float* __restrict__ wep_b,
    const float* __restrict__ wnc_W, const float* __restrict__ wnc_b,
    const float* __restrict__ mb_W,  const float* __restrict__ mb_b,
    const float* __restrict__ wnd_W, const float* __restrict__ wnd_b,
    const float* __restrict__ wne_W, const float* __restrict__ wne_b)
{
    const float* W = nullptr; const float* bias = nullptr; float* outp;
    int nstride = 1, noff = 0, ldw = 1024, ld_out = 1024, small = 0;
    switch (blockIdx.z) {
        case 0: W = wch_W; bias = wch_b; outp = g_wch; break;
        case 1: W = vch_W; bias = vch_b; outp = g_vch; break;
        case 2: W = vep_W; bias = vep_b; outp = g_vep0; ldw = 4096; nstride = 4; noff = 0; break;
        case 3: W = vep_W; bias = vep_b; outp = g_vep2; ldw = 4096; nstride = 4; noff = 2; break;
        case 7: small = 1; outp = g_small; ld_out = 264; break;
        default: { int k = blockIdx.z - 4;
                   W = m_W + k*NC*1024; bias = m_Wb + k*1024; outp = g_Wk + k*NB*1024; } break;
    }
    if (small && blockIdx.x >= 3) return;

    const int n0 = blockIdx.x * 128;
    const int m0 = blockIdx.y * 128;

    extern __shared__ __align__(16) float smem[];
    uint32_t* Ah = reinterpret_cast<uint32_t*>(smem + OFF_AHI);
    uint32_t* Al = reinterpret_cast<uint32_t*>(smem + OFF_ALO);
    uint32_t* Bh = reinterpret_cast<uint32_t*>(smem + OFF_BHI);
    uint32_t* Bl = reinterpret_cast<uint32_t*>(smem + OFF_BLO);
    float*    bias_s = smem + OFF_BIAS;

    const int tid  = threadIdx.x;
    const int wid  = tid >> 5, lane = tid & 31;
    const int g    = lane >> 2, tq = lane & 3;
    const int wm   = wid >> 1, wn = wid & 1;

    // ---- per-thread fixed loader geometry ----
    // A: k fixed = tid&31, m = (tid>>5) + it*8
    // B: n fixed = tid&127, k = (tid>>7) + it*2
    const int kA     = tid & 31;
    const int mAbase = tid >> 5;
    const int nloc   = tid & 127;
    const int kBbase = tid >> 7;

    const float* baseB = nullptr; int strideB = 0;
    {
        int ng = n0 + nloc;
        if (small) {
            if (ng < 258) baseB = sp_col(ng, strideB, mod_W, wdl_W, wep_W, wnc_W, mb_W, wnd_W, wne_W);
        } else {
            baseB = W + (size_t)ng*nstride + noff;
            strideB = ldw;
        }
    }
    const float* baseA = ctx + (size_t)(m0 + mAbase)*NC + kA;

    if (tid < 128) {
        float bv;
        if (small) bv = (n0 + tid < 258) ? sp_bias(n0+tid, mod_b, wdl_b, wep_b, wnc_b, mb_b, wnd_b, wne_b) : 0.f;
        else       bv = bias[(n0+tid)*nstride + noff];
        bias_s[tid] = bv;
    }

    float c[2][8][4];
    #pragma unroll
    for (int mi = 0; mi < 2; mi++)
        #pragma unroll
        for (int ni = 0; ni < 8; ni++)
            #pragma unroll
            for (int q = 0; q < 4; q++) c[mi][ni][q] = 0.f;

    // ---- prologue: chunk 0 into registers ----
    float fA[16], fB[16];
    #pragma unroll
    for (int it = 0; it < 16; it++) fA[it] = baseA[(size_t)it*8*NC];
    #pragma unroll
    for (int it = 0; it < 16; it++)
        fB[it] = baseB ? baseB[(size_t)(kBbase + it*2)*strideB] : 0.f;

    for (int chunk = 0; chunk < 4; chunk++) {
        // split + store current chunk
        #pragma unroll
        for (int it = 0; it < 16; it++) {
            int m = mAbase + it*8;
            tf32split_(fA[it], Ah[m*PA + kA], Al[m*PA + kA]);
        }
        #pragma unroll
        for (int it = 0; it < 16; it++) {
            int k = kBbase + it*2;
            tf32split_(fB[it], Bh[k*PB + nloc], Bl[k*PB + nloc]);
        }
        __syncthreads();

        // prefetch next chunk during mma
        if (chunk < 3) {
            const int kc = (chunk+1)*32;
            #pragma unroll
            for (int it = 0; it < 16; it++) fA[it] = baseA[(size_t)it*8*NC + kc];
            #pragma unroll
            for (int it = 0; it < 16; it++)
                fB[it] = baseB ? baseB[(size_t)(kc + kBbase + it*2)*strideB] : 0.f;
        }

        #pragma unroll
        for (int term = 0; term < 3; term++) {
            const uint32_t* As = (term == 2) ? Al : Ah;
            const uint32_t* Bs = (term == 1) ? Bl : Bh;
            #pragma unroll
            for (int kb = 0; kb < 32; kb += 8) {
                uint32_t a[2][4];
                #pragma unroll
                for (int mi = 0; mi < 2; mi++) {
                    int r0 = wm*32 + mi*16 + g;
                    a[mi][0] = As[(r0    )*PA + kb + tq];
                    a[mi][1] = As[(r0 + 8)*PA + kb + tq];
                    a[mi][2] = As[(r0    )*PA + kb + tq + 4];
                    a[mi][3] = As[(r0 + 8)*PA + kb + tq + 4];
                }
                #pragma unroll
                for (int ni = 0; ni < 8; ni++) {
                    int nb = wn*64 + ni*8 + g;
                    uint32_t b0 = Bs[(kb + tq    )*PB + nb];
                    uint32_t b1 = Bs[(kb + tq + 4)*PB + nb];
                    mma_tf32_(c[0][ni], a[0], b0, b1);
                    mma_tf32_(c[1][ni], a[1], b0, b1);
                }
            }
        }
        __syncthreads();
    }

    // ---- epilogue: stage warp tile 32x65, coalesced out ----
    float* stage = smem + wid*(32*65);
    #pragma unroll
    for (int mi = 0; mi < 2; mi++)
        #pragma unroll
        for (int ni = 0; ni < 8; ni++) {
            int r0 = mi*16 + g;
            int cc = ni*8 + 2*tq;
            stage[(r0    )*65 + cc    ] = c[mi][ni][0];
            stage[(r0    )*65 + cc + 1] = c[mi][ni][1];
            stage[(r0 + 8)*65 + cc    ] = c[mi][ni][2];
            stage[(r0 + 8)*65 + cc + 1] = c[mi][ni][3];
        }
    __syncwarp();
    const int ncol = wn*64;
    const int cg0 = n0 + ncol + lane;
    const int cg1 = cg0 + 32;
    #pragma unroll 4
    for (int r = 0; r < 32; r++) {
        int m = m0 + wm*32 + r;
        float v0 = stage[r*65 + lane]      + bias_s[ncol + lane];
        float v1 = stage[r*65 + 32 + lane] + bias_s[ncol + 32 + lane];
        if (!small || cg0 < 258) outp[(size_t)m*ld_out + cg0] = v0;
        if (!small || cg1 < 258) outp[(size_t)m*ld_out + cg1] = v1;
    }
}

// =====================================================================
// Kernel 2: per-batch fused kernel (unchanged from R12, 139.5us).
// =====================================================================
__global__ __launch_bounds__(256, 4) void scan_kernel(
    const float* __restrict__ form, float* __restrict__ out)
{
    const int b    = blockIdx.x;
    const int tid  = threadIdx.x;
    const int lane = tid & 31, wid = tid >> 5;

    __shared__ __align__(16) float form_t[32][68];
    __shared__ __align__(16) float big[3072];
    __shared__ float match_s[32][16];
    __shared__ float cw_s[96*32];
    __shared__ float segp_s[256];
    __shared__ __align__(16) float sym_s[32][64];
    __shared__ float sm_s[264];
    __shared__ float wnc_s[64];
    __shared__ float mod0_s[16], wdl_s[16], wep0_s[16], wep2_s[16];
    __shared__ float g_s[96], posn_s[96];
    __shared__ float scal2[2];

    for (int i = tid; i < 2048; i += 256) form_t[i & 31][i >> 5] = form[b*2048 + i];
    for (int j = tid; j < 258; j += 256) sm_s[j] = g_small[b*264 + j];
    for (int i = tid; i < 3072; i += 256)
        big[i] = g_Wk[(i >> 10)*(NB*1024) + b*1024 + (i & 1023)];
    __syncthreads();

    if (tid < 16) {
        float m[6], mx = -1e30f;
        #pragma unroll
        for (int ch = 0; ch < 6; ch++) { m[ch] = sm_s[tid*6+ch]; mx = fmaxf(mx, m[ch]); }
        float s = 0.f;
        #pragma unroll
        for (int ch = 0; ch < 6; ch++) { m[ch] = __expf(m[ch]-mx); s += m[ch]; }
        float inv = 1.f/s;
        mod0_s[tid] = m[0]*inv;
        wdl_s[tid]  = m[1]*inv*sm_s[96+tid];
        wep0_s[tid] = m[2]*inv*sm_s[112+tid];
        wep2_s[tid] = m[4]*inv*sm_s[128+tid];
    } else if (tid >= 64 && tid < 128) {
        wnc_s[tid-64] = __expf(sm_s[144 + tid-64]);
    } else if (tid == 128) scal2[0] = __expf(sm_s[256]);
    else if (tid == 129)   scal2[1] = __expf(sm_s[257]);

    {
        const int p0 = wid, p1 = wid + 8, r = lane;
        float prod0 = 1.f, prod1 = 1.f;
        #pragma unroll
        for (int k = 0; k < 3; k++) {
            float sa = sm_s[208 + k*16 + p0];
            float sb = sm_s[208 + k*16 + p1];
            int rr = r + k - 1;
            if (rr >= 0 && rr < 32) {
                const float* w0p = &big[k*1024 + p0*64];
                const float* w1p = &big[k*1024 + p1*64];
                float sa2 = 0.f, sb2 = 0.f;
                #pragma unroll 8
                for (int f = 0; f < 64; f += 8) {
                    float4 fv = *(const float4*)&form_t[rr][f];
                    float4 w0 = *(const float4*)&w0p[f];
                    float4 w1 = *(const float4*)&w1p[f];
                    sa  += w0.x*fv.x + w0.y*fv.y + w0.z*fv.z + w0.w*fv.w;
                    sb  += w1.x*fv.x + w1.y*fv.y + w1.z*fv.z + w1.w*fv.w;
                    float4 fv2 = *(const float4*)&form_t[rr][f+4];
                    float4 w02 = *(const float4*)&w0p[f+4];
                    float4 w12 = *(const float4*)&w1p[f+4];
                    sa2 += w02.x*fv2.x + w02.y*fv2.y + w02.z*fv2.z + w02.w*fv2.w;
                    sb2 += w12.x*fv2.x + w12.y*fv2.y + w12.z*fv2.z + w12.w*fv2.w;
                }
                sa += sa2; sb += sb2;
            }
            prod0 *= sigmoidf_(sa);
            prod1 *= sigmoidf_(sb);
        }
        match_s[r][p0] = prod0;
        match_s[r][p1] = prod1;
    }
    __syncthreads();

    {
        const float* pwch = g_wch + b*1024;
        const float* pvch = g_vch + b*1024;
        for (int i = tid; i < 1024; i += 256) {
            float u1 = mod0_s[i >> 6]*pwch[i];
            big[i]        = u1;
            big[1024 + i] = fmaxf(u1, 0.f)*pvch[i];
        }
    }
    if (tid < 96) {
        int i = tid/3, ph = tid - 3*i;
        const float* wv = (ph == 0) ? wep0_s : (ph == 1 ? wdl_s : wep2_s);
        float s = 0.f;
        #pragma unroll
        for (int p = 0; p < 16; p++) s += match_s[i][p]*wv[p];
        g_s[tid] = (ph == 1) ? (1.f - sigmoidf_(s - scal2[0]))
                             : sigmoidf_(s - scal2[1]);
    }
    __syncthreads();

    if (wid == 0) {
        float a0 = g_s[lane*3+0], a1 = g_s[lane*3+1], a2 = g_s[lane*3+2];
        float loc = a0 + a1 + a2;
        float sc = loc;
        #pragma unroll
        for (int off = 1; off < 32; off <<= 1) {
            float v = __shfl_up_sync(0xffffffffu, sc, off);
            if (lane >= off) sc += v;
        }
        float excl = sc - loc;
        posn_s[lane*3+0] = excl;
        posn_s[lane*3+1] = excl + a0;
        posn_s[lane*3+2] = excl + a0 + a1;
    }
    __syncthreads();

    #pragma unroll 4
    for (int k2 = 0; k2 < 12; k2++) {
        int st = wid*12 + k2;
        float pp = posn_s[st];
        float d  = pp - (float)lane;
        float rstar = fminf(fmaxf(rintf(pp), 0.f), 31.f);
        float dm = pp - rstar;
        float mx = -2.f*dm*dm;
        float e  = __expf(-2.f*d*d - mx);
        float ssum = e;
        #pragma unroll
        for (int off = 16; off; off >>= 1) ssum += __shfl_xor_sync(0xffffffffu, ssum, off);
        cw_s[st*32 + lane] = g_s[st]*e/ssum;
    }
    __syncthreads();

    {
        int st0 = wid*12;
        float run = 1.f;
        #pragma unroll
        for (int k2 = 11; k2 >= 0; k2--) {
            float cc = cw_s[(st0+k2)*32 + lane];
            cw_s[(st0+k2)*32 + lane] = cc*run;
            run *= (1.f - cc);
        }
        segp_s[wid*32 + lane] = run;
    }
    __syncthreads();
    {
        float mult = 1.f;
        #pragma unroll
        for (int w2 = 7; w2 >= 1; w2--) {
            float sp = segp_s[w2*32 + lane];
            if (w2 > wid) mult *= sp;
        }
        if (mult != 1.f) {
            int st0 = wid*12;
            #pragma unroll
            for (int k2 = 0; k2 < 12; k2++)
                cw_s[(st0+k2)*32 + lane] *= mult;
        }
    }
    __syncthreads();

    {
        int f4 = tid & 15, ii = tid >> 4;
        int f = f4*4;
        for (int rep = 0; rep < 2; rep++) {
            int i = ii + rep*16;
            float4 s1 = {0,0,0,0}, s2 = {0,0,0,0};
            #pragma unroll 8
            for (int p = 0; p < 16; p++) {
                float m = match_s[i][p];
                float4 u1 = *(const float4*)&big[p*64 + f];
                float4 u2 = *(const float4*)&big[1024 + p*64 + f];
                s1.x += m*u1.x; s1.y += m*u1.y; s1.z += m*u1.z; s1.w += m*u1.w;
                s2.x += m*u2.x; s2.y += m*u2.y; s2.z += m*u2.z; s2.w += m*u2.w;
            }
            float4 sy = *(const float4*)&form_t[i][f];
            float4 v;
            v.x = sy.x + sigmoidf_(s1.x - wnc_s[f  ])*(s2.x - sy.x);
            v.y = sy.y + sigmoidf_(s1.y - wnc_s[f+1])*(s2.y - sy.y);
            v.z = sy.z + sigmoidf_(s1.z - wnc_s[f+2])*(s2.z - sy.z);
            v.w = sy.w + sigmoidf_(s1.w - wnc_s[f+3])*(s2.w - sy.w);
            *(float4*)&sym_s[i][f] = v;
        }
    }
    __syncthreads();

    float* M0 = &form_t[0][0];
    float* M2 = M0 + 512;
    {
        const float* pv0 = g_vep0 + b*1024;
        const float* pv2 = g_vep2 + b*1024;
        for (int i = tid; i < 1024; i += 256) {
            int p = i >> 6;
            big[i]        = fmaxf(wep0_s[p], 0.f)*pv0[i];
            big[1024 + i] = fmaxf(wep2_s[p], 0.f)*pv2[i];
        }
    }
    {
        int p0 = wid, p1 = wid + 8;
        float a00 = 0.f, a01 = 0.f, a20 = 0.f, a21 = 0.f;
        #pragma unroll 8
        for (int i = 0; i < 32; i++) {
            float w0 = cw_s[(3*i  )*32 + lane];
            float w2 = cw_s[(3*i+2)*32 + lane];
            float m0 = match_s[i][p0], m1v = match_s[i][p1];
            a00 += m0*w0;  a01 += m1v*w0;
            a20 += m0*w2;  a21 += m1v*w2;
        }
        M0[p0*32 + lane] = a00; M0[p1*32 + lane] = a01;
        M2[p0*32 + lane] = a20; M2[p1*32 + lane] = a21;
    }
    __syncthreads();

    const int fb = wid*8;
    {
        float o0=0.f,o1=0.f,o2=0.f,o3=0.f,o4=0.f,o5=0.f,o6=0.f,o7=0.f;
        #pragma unroll 8
        for (int p = 0; p < 16; p++) {
            float a0 = M0[p*32 + lane];
            float a2 = M2[p*32 + lane];
            float4 v00 = *(const float4*)&big[p*64 + fb];
            float4 v01 = *(const float4*)&big[p*64 + fb + 4];
            float4 v20 = *(const float4*)&big[1024 + p*64 + fb];
            float4 v21 = *(const float4*)&big[1024 + p*64 + fb + 4];
            o0 += a0*v00.x + a2*v20.x;  o1 += a0*v00.y + a2*v20.y;
            o2 += a0*v00.z + a2*v20.z;  o3 += a0*v00.w + a2*v20.w;
            o4 += a0*v01.x + a2*v21.x;  o5 += a0*v01.y + a2*v21.y;
            o6 += a0*v01.z + a2*v21.z;  o7 += a0*v01.w + a2*v21.w;
        }
        #pragma unroll 8
        for (int i = 0; i < 32; i++) {
            float w1 = cw_s[(3*i+1)*32 + lane];
            float4 s0 = *(const float4*)&sym_s[i][fb];
            float4 s1v = *(const float4*)&sym_s[i][fb + 4];
            o0 += w1*s0.x;  o1 += w1*s0.y;  o2 += w1*s0.z;  o3 += w1*s0.w;
            o4 += w1*s1v.x; o5 += w1*s1v.y; o6 += w1*s1v.z; o7 += w1*s1v.w;
        }
        out[b*2048 + (fb  )*32 + lane] = o0;
        out[b*2048 + (fb+1)*32 + lane] = o1;
        out[b*2048 + (fb+2)*32 + lane] = o2;
        out[b*2048 + (fb+3)*32 + lane] = o3;
        out[b*2048 + (fb+4)*32 + lane] = o4;
        out[b*2048 + (fb+5)*32 + lane] = o5;
        out[b*2048 + (fb+6)*32 + lane] = o6;
        out[b*2048 + (fb+7)*32 + lane] = o7;
    }
}

// =====================================================================
extern "C" void kernel_launch(void* const* d_in, const int* in_sizes, int n_in,
                              void* d_out, int out_size)
{
    (void)in_sizes; (void)n_in; (void)out_size;
    const float* form  = (const float*)d_in[0];
    const float* ctx   = (const float*)d_in[1];
    const float* mod_W = (const float*)d_in[2];
    const float* mod_b = (const float*)d_in[3];
    const float* wch_W = (const float*)d_in[4];
    const float* wch_b = (const float*)d_in[5];
    const float* wdl_W = (const float*)d_in[6];
    const float* wdl_b = (const float*)d_in[7];
    const float* wep_W = (const float*)d_in[8];
    const float* wep_b = (const float*)d_in[9];
    const float* vch_W = (const float*)d_in[10];
    const float* vch_b = (const float*)d_in[11];
    const float* vep_W = (const float*)d_in[12];
    const float* vep_b = (const float*)d_in[13];
    const float* wnc_W = (const float*)d_in[14];
    const float* wnc_b = (const float*)d_in[15];
    const float* wnd_W = (const float*)d_in[16];
    const float* wnd_b = (const float*)d_in[17];
    const float* wne_W = (const float*)d_in[18];
    const float* wne_b = (const float*)d_in[19];
    const float* m_W   = (const float*)d_in[20];
    const float* m_Wb  = (const float*)d_in[21];
    const float* mb_W  = (const float*)d_in[22];
    const float* mb_b  = (const float*)d_in[23];

    static int smem_set = 0;
    if (!smem_set) {
        cudaFuncSetAttribute(proj_tc, cudaFuncAttributeMaxDynamicSharedMemorySize, SM_BYTES);
        smem_set = 1;
    }

    dim3 ggrid(1024/128, NB/128, 8);
    proj_tc<<<ggrid, 256, SM_BYTES>>>(ctx, wch_W, wch_b, vch_W, vch_b, vep_W, vep_b,
                                      m_W, m_Wb,
                                      mod_W, mod_b, wdl_W, wdl_b, wep_W, wep_b,
                                      wnc_W, wnc_b, mb_W, mb_b, wnd_W, wnd_b, wne_W, wne_b);

    scan_kernel<<<NB, 256>>>(form, (float*)d_out);
}

// round 14
// speedup vs baseline: 1.1139x; 1.1139x over previous
#include <cuda_runtime.h>
#include <cstdint>

#define NB 2048
#define NF 64
#define NR 32
#define NP 16
#define NC 128

// ---------------- scratch ----------------
__device__ float g_wch [NB*1024];
__device__ float g_vch [NB*1024];
__device__ float g_vep0[NB*1024];
__device__ float g_vep2[NB*1024];
__device__ float g_Wk  [3*NB*1024];
__device__ float g_small[NB*264];

__device__ __forceinline__ float sigmoidf_(float x) { return 1.f/(1.f + __expf(-x)); }

// ---- 3xTF32 helpers (family-portable PTX, sm_80+) ----
__device__ __forceinline__ void tf32split_(float x, uint32_t& hi, uint32_t& lo) {
    uint32_t h;
    asm("cvt.rna.tf32.f32 %0, %1;" : "=r"(h) : "f"(x));
    float r = x - __uint_as_float(h);
    uint32_t l;
    asm("cvt.rna.tf32.f32 %0, %1;" : "=r"(l) : "f"(r));
    hi = h; lo = l;
}
__device__ __forceinline__ void mma_tf32_(float* c, const uint32_t* a, uint32_t b0, uint32_t b1) {
    asm volatile(
        "mma.sync.aligned.m16n8k8.row.col.f32.tf32.tf32.f32 "
        "{%0,%1,%2,%3}, {%4,%5,%6,%7}, {%8,%9}, {%0,%1,%2,%3};"
        : "+f"(c[0]), "+f"(c[1]), "+f"(c[2]), "+f"(c[3])
        : "r"(a[0]), "r"(a[1]), "r"(a[2]), "r"(a[3]), "r"(b0), "r"(b1));
}

// ---- small-projection column map (258 cols) ----
__device__ __forceinline__ const float* sp_col(int n, int& stride,
    const float* mod_W, const float* wdl_W, const float* wep_W,
    const float* wnc_W, const float* mb_W, const float* wnd_W, const float* wne_W)
{
    if (n < 96)  { stride = 96; return mod_W + n; }
    if (n < 112) { stride = 16; return wdl_W + (n-96); }
    if (n < 128) { stride = 64; return wep_W + (n-112)*4; }
    if (n < 144) { stride = 64; return wep_W + (n-128)*4 + 2; }
    if (n < 208) { stride = 64; return wnc_W + (n-144); }
    if (n < 256) { int idx = n-208; stride = 16; return mb_W + (idx>>4)*2048 + (idx&15); }
    if (n == 256){ stride = 1; return wnd_W; }
    stride = 1; return wne_W;
}
__device__ __forceinline__ float sp_bias(int n,
    const float* mod_b, const float* wdl_b, const float* wep_b,
    const float* wnc_b, const float* mb_b, const float* wnd_b, const float* wne_b)
{
    if (n < 96)  return mod_b[n];
    if (n < 112) return wdl_b[n-96];
    if (n < 128) return wep_b[(n-112)*4];
    if (n < 144) return wep_b[(n-128)*4 + 2];
    if (n < 208) return wnc_b[n-144];
    if (n < 256) return mb_b[n-208];
    if (n == 256) return wnd_b[0];
    return wne_b[0];
}

// smem layout (floats): A stride 36, B stride 136.
#define PA 36
#define PB 136
#define OFF_AHI 0
#define OFF_ALO (128*PA)
#define OFF_BHI (2*128*PA)
#define OFF_BLO (2*128*PA + 32*PB)
#define OFF_BIAS (2*128*PA + 2*32*PB)
#define SM_FLOATS (OFF_BIAS + 128)
#define SM_BYTES  (SM_FLOATS*4)

// =====================================================================
// Kernel 1: 7 big GEMMs + small-proj gather GEMM. 3xTF32 mma.sync.
// R12 body (proven 27.5us/wave), 1D-packed grid: 944 real CTAs, no
// dead blocks. [0,896): z = bid>>7; [896,944): small slice.
// =====================================================================
__global__ __launch_bounds__(256) void proj_tc(
    const float* __restrict__ ctx,
    const float* __restrict__ wch_W, const float* __restrict__ wch_b,
    const float* __restrict__ vch_W, const float* __restrict__ vch_b,
    const float* __restrict__ vep_W, const float* __restrict__ vep_b,
    const float* __restrict__ m_W,   const float* __restrict__ m_Wb,
    const float* __restrict__ mod_W, const float* __restrict__ mod_b,
    const float* __restrict__ wdl_W, const float* __restrict__ wdl_b,
    const float* __restrict__ wep_W, const float* __restrict__ wep_b,
    const float* __restrict__ wnc_W, const float* __restrict__ wnc_b,
    const float* __restrict__ mb_W,  const float* __restrict__ mb_b,
    const float* __restrict__ wnd_W, const float* __restrict__ wnd_b,
    const float* __restrict__ wne_W, const float* __restrict__ wne_b)
{
    // ---- 1D grid decode ----
    const int bid = blockIdx.x;
    int bz, bx, by;
    if (bid < 896) { bz = bid >> 7; int rem = bid & 127; bx = rem >> 4; by = rem & 15; }
    else           { bz = 7; int rem = bid - 896; bx = rem >> 4; by = rem & 15; }

    const float* W = nullptr; const float* bias = nullptr; float* outp;
    int nstride = 1, noff = 0, ldw = 1024, ld_out = 1024, small = 0;
    switch (bz) {
        case 0: W = wch_W; bias = wch_b; outp = g_wch; break;
        case 1: W = vch_W; bias = vch_b; outp = g_vch; break;
        case 2: W = vep_W; bias = vep_b; outp = g_vep0; ldw = 4096; nstride = 4; noff = 0; break;
        case 3: W = vep_W; bias = vep_b; outp = g_vep2; ldw = 4096; nstride = 4; noff = 2; break;
        case 7: small = 1; outp = g_small; ld_out = 264; break;
        default: { int k = bz - 4;
                   W = m_W + k*NC*1024; bias = m_Wb + k*1024; outp = g_Wk + k*NB*1024; } break;
    }

    const int n0 = bx * 128;
    const int m0 = by * 128;

    extern __shared__ __align__(16) float smem[];
    uint32_t* Ah = reinterpret_cast<uint32_t*>(smem + OFF_AHI);
    uint32_t* Al = reinterpret_cast<uint32_t*>(smem + OFF_ALO);
    uint32_t* Bh = reinterpret_cast<uint32_t*>(smem + OFF_BHI);
    uint32_t* Bl = reinterpret_cast<uint32_t*>(smem + OFF_BLO);
    float*    bias_s = smem + OFF_BIAS;

    const int tid  = threadIdx.x;
    const int wid  = tid >> 5, lane = tid & 31;
    const int g    = lane >> 2, tq = lane & 3;
    const int wm   = wid >> 1, wn = wid & 1;

    if (tid < 128) {
        float bv;
        if (small) bv = (n0 + tid < 258) ? sp_bias(n0+tid, mod_b, wdl_b, wep_b, wnc_b, mb_b, wnd_b, wne_b) : 0.f;
        else       bv = bias[(n0+tid)*nstride + noff];
        bias_s[tid] = bv;
    }

    float c[2][8][4];
    #pragma unroll
    for (int mi = 0; mi < 2; mi++)
        #pragma unroll
        for (int ni = 0; ni < 8; ni++)
            #pragma unroll
            for (int q = 0; q < 4; q++) c[mi][ni][q] = 0.f;

    for (int chunk = 0; chunk < 4; chunk++) {
        const int kc = chunk*32;
        if (chunk) __syncthreads();

        #pragma unroll
        for (int it = 0; it < 16; it++) {
            int i = tid + it*256;
            int m = i >> 5, k = i & 31;
            float v = ctx[(m0+m)*NC + kc + k];
            tf32split_(v, Ah[m*PA + k], Al[m*PA + k]);
        }
        if (small) {
            #pragma unroll
            for (int it = 0; it < 16; it++) {
                int i = tid + it*256;
                int k = i >> 7, n = i & 127;
                int ng = n0 + n;
                float v = 0.f;
                if (ng < 258) {
                    int stride;
                    const float* p = sp_col(ng, stride, mod_W, wdl_W, wep_W, wnc_W, mb_W, wnd_W, wne_W);
                    v = p[(kc+k)*stride];
                }
                tf32split_(v, Bh[k*PB + n], Bl[k*PB + n]);
            }
        } else if (nstride == 1) {
            #pragma unroll
            for (int it = 0; it < 16; it++) {
                int i = tid + it*256;
                int k = i >> 7, n = i & 127;
                float v = W[(kc+k)*ldw + n0 + n];
                tf32split_(v, Bh[k*PB + n], Bl[k*PB + n]);
            }
        } else {
            #pragma unroll
            for (int it = 0; it < 16; it++) {
                int i = tid + it*256;
                int k = i >> 7, n = i & 127;
                float4 w4 = *(const float4*)&W[(kc+k)*4096 + (n0+n)*4];
                float v = (noff == 0) ? w4.x : w4.z;
                tf32split_(v, Bh[k*PB + n], Bl[k*PB + n]);
            }
        }
        __syncthreads();

        #pragma unroll
        for (int term = 0; term < 3; term++) {
            const uint32_t* As = (term == 2) ? Al : Ah;
            const uint32_t* Bs = (term == 1) ? Bl : Bh;
            #pragma unroll
            for (int kb = 0; kb < 32; kb += 8) {
                uint32_t a[2][4];
                #pragma unroll
                for (int mi = 0; mi < 2; mi++) {
                    int r0 = wm*32 + mi*16 + g;
                    a[mi][0] = As[(r0    )*PA + kb + tq];
                    a[mi][1] = As[(r0 + 8)*PA + kb + tq];
                    a[mi][2] = As[(r0    )*PA + kb + tq + 4];
                    a[mi][3] = As[(r0 + 8)*PA + kb + tq + 4];
                }
                #pragma unroll
                for (int ni = 0; ni < 8; ni++) {
                    int nb = wn*64 + ni*8 + g;
                    uint32_t b0 = Bs[(kb + tq    )*PB + nb];
                    uint32_t b1 = Bs[(kb + tq + 4)*PB + nb];
                    mma_tf32_(c[0][ni], a[0], b0, b1);
                    mma_tf32_(c[1][ni], a[1], b0, b1);
                }
            }
        }
    }
    __syncthreads();

    // ---- epilogue: stage warp tile 32x65, coalesced out ----
    float* stage = smem + wid*(32*65);
    #pragma unroll
    for (int mi = 0; mi < 2; mi++)
        #pragma unroll
        for (int ni = 0; ni < 8; ni++) {
            int r0 = mi*16 + g;
            int cc = ni*8 + 2*tq;
            stage[(r0    )*65 + cc    ] = c[mi][ni][0];
            stage[(r0    )*65 + cc + 1] = c[mi][ni][1];
            stage[(r0 + 8)*65 + cc    ] = c[mi][ni][2];
            stage[(r0 + 8)*65 + cc + 1] = c[mi][ni][3];
        }
    __syncwarp();
    const int ncol = wn*64;
    const int cg0 = n0 + ncol + lane;
    const int cg1 = cg0 + 32;
    #pragma unroll 4
    for (int r = 0; r < 32; r++) {
        int m = m0 + wm*32 + r;
        float v0 = stage[r*65 + lane]      + bias_s[ncol + lane];
        float v1 = stage[r*65 + 32 + lane] + bias_s[ncol + 32 + lane];
        if (!small || cg0 < 258) outp[(size_t)m*ld_out + cg0] = v0;
        if (!small || cg1 < 258) outp[(size_t)m*ld_out + cg1] = v1;
    }
}

// =====================================================================
// Kernel 2: per-batch fused kernel (R12 + float2-interleaved M0/M2).
// =====================================================================
__global__ __launch_bounds__(256, 4) void scan_kernel(
    const float* __restrict__ form, float* __restrict__ out)
{
    const int b    = blockIdx.x;
    const int tid  = threadIdx.x;
    const int lane = tid & 31, wid = tid >> 5;

    __shared__ __align__(16) float form_t[32][68];
    __shared__ __align__(16) float big[3072];
    __shared__ float match_s[32][16];
    __shared__ float cw_s[96*32];
    __shared__ float segp_s[256];
    __shared__ __align__(16) float sym_s[32][64];
    __shared__ float sm_s[264];
    __shared__ float wnc_s[64];
    __shared__ float mod0_s[16], wdl_s[16], wep0_s[16], wep2_s[16];
    __shared__ float g_s[96], posn_s[96];
    __shared__ float scal2[2];

    for (int i = tid; i < 2048; i += 256) form_t[i & 31][i >> 5] = form[b*2048 + i];
    for (int j = tid; j < 258; j += 256) sm_s[j] = g_small[b*264 + j];
    for (int i = tid; i < 3072; i += 256)
        big[i] = g_Wk[(i >> 10)*(NB*1024) + b*1024 + (i & 1023)];
    __syncthreads();

    if (tid < 16) {
        float m[6], mx = -1e30f;
        #pragma unroll
        for (int ch = 0; ch < 6; ch++) { m[ch] = sm_s[tid*6+ch]; mx = fmaxf(mx, m[ch]); }
        float s = 0.f;
        #pragma unroll
        for (int ch = 0; ch < 6; ch++) { m[ch] = __expf(m[ch]-mx); s += m[ch]; }
        float inv = 1.f/s;
        mod0_s[tid] = m[0]*inv;
        wdl_s[tid]  = m[1]*inv*sm_s[96+tid];
        wep0_s[tid] = m[2]*inv*sm_s[112+tid];
        wep2_s[tid] = m[4]*inv*sm_s[128+tid];
    } else if (tid >= 64 && tid < 128) {
        wnc_s[tid-64] = __expf(sm_s[144 + tid-64]);
    } else if (tid == 128) scal2[0] = __expf(sm_s[256]);
    else if (tid == 129)   scal2[1] = __expf(sm_s[257]);

    {
        const int p0 = wid, p1 = wid + 8, r = lane;
        float prod0 = 1.f, prod1 = 1.f;
        #pragma unroll
        for (int k = 0; k < 3; k++) {
            float sa = sm_s[208 + k*16 + p0];
            float sb = sm_s[208 + k*16 + p1];
            int rr = r + k - 1;
            if (rr >= 0 && rr < 32) {
                const float* w0p = &big[k*1024 + p0*64];
                const float* w1p = &big[k*1024 + p1*64];
                float sa2 = 0.f, sb2 = 0.f;
                #pragma unroll 8
                for (int f = 0; f < 64; f += 8) {
                    float4 fv = *(const float4*)&form_t[rr][f];
                    float4 w0 = *(const float4*)&w0p[f];
                    float4 w1 = *(const float4*)&w1p[f];
                    sa  += w0.x*fv.x + w0.y*fv.y + w0.z*fv.z + w0.w*fv.w;
                    sb  += w1.x*fv.x + w1.y*fv.y + w1.z*fv.z + w1.w*fv.w;
                    float4 fv2 = *(const float4*)&form_t[rr][f+4];
                    float4 w02 = *(const float4*)&w0p[f+4];
                    float4 w12 = *(const float4*)&w1p[f+4];
                    sa2 += w02.x*fv2.x + w02.y*fv2.y + w02.z*fv2.z + w02.w*fv2.w;
                    sb2 += w12.x*fv2.x + w12.y*fv2.y + w12.z*fv2.z + w12.w*fv2.w;
                }
                sa += sa2; sb += sb2;
            }
            prod0 *= sigmoidf_(sa);
            prod1 *= sigmoidf_(sb);
        }
        match_s[r][p0] = prod0;
        match_s[r][p1] = prod1;
    }
    __syncthreads();

    {
        const float* pwch = g_wch + b*1024;
        const float* pvch = g_vch + b*1024;
        for (int i = tid; i < 1024; i += 256) {
            float u1 = mod0_s[i >> 6]*pwch[i];
            big[i]        = u1;
            big[1024 + i] = fmaxf(u1, 0.f)*pvch[i];
        }
    }
    if (tid < 96) {
        int i = tid/3, ph = tid - 3*i;
        const float* wv = (ph == 0) ? wep0_s : (ph == 1 ? wdl_s : wep2_s);
        float s = 0.f;
        #pragma unroll
        for (int p = 0; p < 16; p++) s += match_s[i][p]*wv[p];
        g_s[tid] = (ph == 1) ? (1.f - sigmoidf_(s - scal2[0]))
                             : sigmoidf_(s - scal2[1]);
    }
    __syncthreads();

    if (wid == 0) {
        float a0 = g_s[lane*3+0], a1 = g_s[lane*3+1], a2 = g_s[lane*3+2];
        float loc = a0 + a1 + a2;
        float sc = loc;
        #pragma unroll
        for (int off = 1; off < 32; off <<= 1) {
            float v = __shfl_up_sync(0xffffffffu, sc, off);
            if (lane >= off) sc += v;
        }
        float excl = sc - loc;
        posn_s[lane*3+0] = excl;
        posn_s[lane*3+1] = excl + a0;
        posn_s[lane*3+2] = excl + a0 + a1;
    }
    __syncthreads();

    #pragma unroll 4
    for (int k2 = 0; k2 < 12; k2++) {
        int st = wid*12 + k2;
        float pp = posn_s[st];
        float d  = pp - (float)lane;
        float rstar = fminf(fmaxf(rintf(pp), 0.f), 31.f);
        float dm = pp - rstar;
        float mx = -2.f*dm*dm;
        float e  = __expf(-2.f*d*d - mx);
        float ssum = e;
        #pragma unroll
        for (int off = 16; off; off >>= 1) ssum += __shfl_xor_sync(0xffffffffu, ssum, off);
        cw_s[st*32 + lane] = g_s[st]*e/ssum;
    }
    __syncthreads();

    {
        int st0 = wid*12;
        float run = 1.f;
        #pragma unroll
        for (int k2 = 11; k2 >= 0; k2--) {
            float cc = cw_s[(st0+k2)*32 + lane];
            cw_s[(st0+k2)*32 + lane] = cc*run;
            run *= (1.f - cc);
        }
        segp_s[wid*32 + lane] = run;
    }
    __syncthreads();
    {
        float mult = 1.f;
        #pragma unroll
        for (int w2 = 7; w2 >= 1; w2--) {
            float sp = segp_s[w2*32 + lane];
            if (w2 > wid) mult *= sp;
        }
        if (mult != 1.f) {
            int st0 = wid*12;
            #pragma unroll
            for (int k2 = 0; k2 < 12; k2++)
                cw_s[(st0+k2)*32 + lane] *= mult;
        }
    }
    __syncthreads();

    {
        int f4 = tid & 15, ii = tid >> 4;
        int f = f4*4;
        for (int rep = 0; rep < 2; rep++) {
            int i = ii + rep*16;
            float4 s1 = {0,0,0,0}, s2 = {0,0,0,0};
            #pragma unroll 8
            for (int p = 0; p < 16; p++) {
                float m = match_s[i][p];
                float4 u1 = *(const float4*)&big[p*64 + f];
                float4 u2 = *(const float4*)&big[1024 + p*64 + f];
                s1.x += m*u1.x; s1.y += m*u1.y; s1.z += m*u1.z; s1.w += m*u1.w;
                s2.x += m*u2.x; s2.y += m*u2.y; s2.z += m*u2.z; s2.w += m*u2.w;
            }
            float4 sy = *(const float4*)&form_t[i][f];
            float4 v;
            v.x = sy.x + sigmoidf_(s1.x - wnc_s[f  ])*(s2.x - sy.x);
            v.y = sy.y + sigmoidf_(s1.y - wnc_s[f+1])*(s2.y - sy.y);
            v.z = sy.z + sigmoidf_(s1.z - wnc_s[f+2])*(s2.z - sy.z);
            v.w = sy.w + sigmoidf_(s1.w - wnc_s[f+3])*(s2.w - sy.w);
            *(float4*)&sym_s[i][f] = v;
        }
    }
    __syncthreads();

    // ---- vep' tables + interleaved M (float2 {M0,M2}) aliasing form_t ----
    float2* Mpair = reinterpret_cast<float2*>(&form_t[0][0]);
    {
        const float* pv0 = g_vep0 + b*1024;
        const float* pv2 = g_vep2 + b*1024;
        for (int i = tid; i < 1024; i += 256) {
            int p = i >> 6;
            big[i]        = fmaxf(wep0_s[p], 0.f)*pv0[i];
            big[1024 + i] = fmaxf(wep2_s[p], 0.f)*pv2[i];
        }
    }
    {
        int p0 = wid, p1 = wid + 8;
        float a00 = 0.f, a01 = 0.f, a20 = 0.f, a21 = 0.f;
        #pragma unroll 8
        for (int i = 0; i < 32; i++) {
            float w0 = cw_s[(3*i  )*32 + lane];
            float w2 = cw_s[(3*i+2)*32 + lane];
            float m0 = match_s[i][p0], m1v = match_s[i][p1];
            a00 += m0*w0;  a01 += m1v*w0;
            a20 += m0*w2;  a21 += m1v*w2;
        }
        Mpair[p0*32 + lane] = make_float2(a00, a20);
        Mpair[p1*32 + lane] = make_float2(a01, a21);
    }
    __syncthreads();

    const int fb = wid*8;
    {
        float o0=0.f,o1=0.f,o2=0.f,o3=0.f,o4=0.f,o5=0.f,o6=0.f,o7=0.f;
        #pragma unroll 8
        for (int p = 0; p < 16; p++) {
            float2 ap = Mpair[p*32 + lane];
            float a0 = ap.x, a2 = ap.y;
            float4 v00 = *(const float4*)&big[p*64 + fb];
            float4 v01 = *(const float4*)&big[p*64 + fb + 4];
            float4 v20 = *(const float4*)&big[1024 + p*64 + fb];
            float4 v21 = *(const float4*)&big[1024 + p*64 + fb + 4];
            o0 += a0*v00.x + a2*v20.x;  o1 += a0*v00.y + a2*v20.y;
            o2 += a0*v00.z + a2*v20.z;  o3 += a0*v00.w + a2*v20.w;
            o4 += a0*v01.x + a2*v21.x;  o5 += a0*v01.y + a2*v21.y;
            o6 += a0*v01.z + a2*v21.z;  o7 += a0*v01.w + a2*v21.w;
        }
        #pragma unroll 8
        for (int i = 0; i < 32; i++) {
            float w1 = cw_s[(3*i+1)*32 + lane];
            float4 s0 = *(const float4*)&sym_s[i][fb];
            float4 s1v = *(const float4*)&sym_s[i][fb + 4];
            o0 += w1*s0.x;  o1 += w1*s0.y;  o2 += w1*s0.z;  o3 += w1*s0.w;
            o4 += w1*s1v.x; o5 += w1*s1v.y; o6 += w1*s1v.z; o7 += w1*s1v.w;
        }
        out[b*2048 + (fb  )*32 + lane] = o0;
        out[b*2048 + (fb+1)*32 + lane] = o1;
        out[b*2048 + (fb+2)*32 + lane] = o2;
        out[b*2048 + (fb+3)*32 + lane] = o3;
        out[b*2048 + (fb+4)*32 + lane] = o4;
        out[b*2048 + (fb+5)*32 + lane] = o5;
        out[b*2048 + (fb+6)*32 + lane] = o6;
        out[b*2048 + (fb+7)*32 + lane] = o7;
    }
}

// =====================================================================
extern "C" void kernel_launch(void* const* d_in, const int* in_sizes, int n_in,
                              void* d_out, int out_size)
{
    (void)in_sizes; (void)n_in; (void)out_size;
    const float* form  = (const float*)d_in[0];
    const float* ctx   = (const float*)d_in[1];
    const float* mod_W = (const float*)d_in[2];
    const float* mod_b = (const float*)d_in[3];
    const float* wch_W = (const float*)d_in[4];
    const float* wch_b = (const float*)d_in[5];
    const float* wdl_W = (const float*)d_in[6];
    const float* wdl_b = (const float*)d_in[7];
    const float* wep_W = (const float*)d_in[8];
    const float* wep_b = (const float*)d_in[9];
    const float* vch_W = (const float*)d_in[10];
    const float* vch_b = (const float*)d_in[11];
    const float* vep_W = (const float*)d_in[12];
    const float* vep_b = (const float*)d_in[13];
    const float* wnc_W = (const float*)d_in[14];
    const float* wnc_b = (const float*)d_in[15];
    const float* wnd_W = (const float*)d_in[16];
    const float* wnd_b = (const float*)d_in[17];
    const float* wne_W = (const float*)d_in[18];
    const float* wne_b = (const float*)d_in[19];
    const float* m_W   = (const float*)d_in[20];
    const float* m_Wb  = (const float*)d_in[21];
    const float* mb_W  = (const float*)d_in[22];
    const float* mb_b  = (const float*)d_in[23];

    static int smem_set = 0;
    if (!smem_set) {
        cudaFuncSetAttribute(proj_tc, cudaFuncAttributeMaxDynamicSharedMemorySize, SM_BYTES);
        smem_set = 1;
    }

    proj_tc<<<944, 256, SM_BYTES>>>(ctx, wch_W, wch_b, vch_W, vch_b, vep_W, vep_b,
                                    m_W, m_Wb,
                                    mod_W, mod_b, wdl_W, wdl_b, wep_W, wep_b,
                                    wnc_W, wnc_b, mb_W, mb_b, wnd_W, wnd_b, wne_W, wne_b);

    scan_kernel<<<NB, 256>>>(form, (float*)d_out);
}